// round 9
// baseline (speedup 1.0000x reference)
#include <cuda_runtime.h>
#include <cstdint>

// out[b, f] = (medians[f] > 0 && inputs[b, f] >= medians[f]) ? 1.0f : 0.0f
// inputs: 8192 x 4096 fp32 (134 MB streamed), medians: 4096 fp32,
// output: float32 (134 MB streamed). DRAM-bound; R6/R7 plateau at 5.66 TB/s.
//
// R8: persistent-style grid (148 SMs x 6 blocks = 888 blocks, 256 threads).
// Each block grid-strides over WHOLE ROWS: per iteration the block touches one
// contiguous 16 KB input burst and one contiguous 16 KB output burst (best
// DRAM row-buffer behavior), with zero wave-quantization tail. The block's
// 4 median float4s per thread are hoisted into registers before the loop, so
// the steady state is pure input-read + output-write.

#define ROW4    1024          // float4 per row (4096 floats)
#define TPB     256
#define BLOCKS  (148 * 6)     // exact residency at ~40 regs/thread
#define NROWS   8192

__device__ __forceinline__ float4 cmp4(float4 a, float4 m) {
    float4 r;
    r.x = (m.x > 0.0f && a.x >= m.x) ? 1.0f : 0.0f;
    r.y = (m.y > 0.0f && a.y >= m.y) ? 1.0f : 0.0f;
    r.z = (m.z > 0.0f && a.z >= m.z) ? 1.0f : 0.0f;
    r.w = (m.w > 0.0f && a.w >= m.w) ? 1.0f : 0.0f;
    return r;
}

__global__ void __launch_bounds__(TPB)
binarize_kernel(const float4* __restrict__ in,
                const float4* __restrict__ med,
                float4* __restrict__ out) {
    unsigned tid = threadIdx.x;

    // Hoist this thread's 4 median float4s (covering the full row across the
    // block) into registers once.
    const float4 m0 = med[tid + 0 * TPB];
    const float4 m1 = med[tid + 1 * TPB];
    const float4 m2 = med[tid + 2 * TPB];
    const float4 m3 = med[tid + 3 * TPB];

    // Grid-stride over rows: block b handles rows b, b+888, b+1776, ...
    for (unsigned row = blockIdx.x; row < NROWS; row += BLOCKS) {
        size_t base = (size_t)row * ROW4 + tid;

        // 4 independent loads in flight (MLP = 4); block covers the full
        // 16 KB row contiguously.
        float4 a0 = __ldcs(&in[base + 0 * TPB]);
        float4 a1 = __ldcs(&in[base + 1 * TPB]);
        float4 a2 = __ldcs(&in[base + 2 * TPB]);
        float4 a3 = __ldcs(&in[base + 3 * TPB]);

        __stcs(&out[base + 0 * TPB], cmp4(a0, m0));
        __stcs(&out[base + 1 * TPB], cmp4(a1, m1));
        __stcs(&out[base + 2 * TPB], cmp4(a2, m2));
        __stcs(&out[base + 3 * TPB], cmp4(a3, m3));
    }
}

extern "C" void kernel_launch(void* const* d_in, const int* in_sizes, int n_in,
                              void* d_out, int out_size) {
    // Defensive: larger tensor = inputs, smaller = medians.
    int ii = 0, mi = 1;
    if (n_in >= 2 && in_sizes[1] > in_sizes[0]) { ii = 1; mi = 0; }

    const float4* in  = (const float4*)d_in[ii];
    const float4* med = (const float4*)d_in[mi];
    float4* out = (float4*)d_out;

    binarize_kernel<<<BLOCKS, TPB>>>(in, med, out);
}

// round 10
// speedup vs baseline: 1.1044x; 1.1044x over previous
#include <cuda_runtime.h>
#include <cstdint>

// out[b, f] = (medians[f] > 0 && inputs[b, f] >= medians[f]) ? 1.0f : 0.0f
// inputs: 8192 x 4096 fp32 (134 MB streamed), medians: 4096 fp32,
// output: float32 (134 MB streamed).
//
// Effective app bandwidth is ~7 TB/s (88% of spec) at 38us kernel time —
// at the mixed 2:1 read/write HBM roofline. R9 = consolidation of the two
// best variants:
//   - R6 shape: RGRP=8, 4096 blocks x 256 thr (best occupancy + wave order)
//   - R7 extras: __ldcs/__stcs streaming hints + load-ahead pipeline
// Column-tiled: every warp LDG.128/STG.128 covers 512 contiguous bytes
// (minimum L1 wavefronts); median float4 register-resident per thread.

#define ROW4   1024   // float4 per row (4096 floats)
#define COLS4  256    // float4 columns per block (= blockDim.x)
#define RGRP   8      // rows per block
#define NROWS  8192

__device__ __forceinline__ float4 cmp4(float4 a, float4 m) {
    float4 r;
    r.x = (m.x > 0.0f && a.x >= m.x) ? 1.0f : 0.0f;
    r.y = (m.y > 0.0f && a.y >= m.y) ? 1.0f : 0.0f;
    r.z = (m.z > 0.0f && a.z >= m.z) ? 1.0f : 0.0f;
    r.w = (m.w > 0.0f && a.w >= m.w) ? 1.0f : 0.0f;
    return r;
}

__global__ void __launch_bounds__(COLS4)
binarize_kernel(const float4* __restrict__ in,
                const float4* __restrict__ med,
                float4* __restrict__ out) {
    // 4 column-groups per row; row-groups in the upper grid bits.
    unsigned cg   = blockIdx.x & 3u;           // quarter of the row
    unsigned rg   = blockIdx.x >> 2;           // row group
    unsigned col4 = cg * COLS4 + threadIdx.x;
    size_t   base = (size_t)rg * RGRP * ROW4 + col4;

    const float4 m = med[col4];                // register-resident across rows

    // Prologue: rows 0..3 in flight.
    float4 a0 = __ldcs(&in[base + 0 * ROW4]);
    float4 a1 = __ldcs(&in[base + 1 * ROW4]);
    float4 a2 = __ldcs(&in[base + 2 * ROW4]);
    float4 a3 = __ldcs(&in[base + 3 * ROW4]);

    // Load rows 4..7 BEFORE storing rows 0..3 (stores never wait on
    // freshly-issued loads).
    size_t nb = base + 4 * (size_t)ROW4;
    float4 b0 = __ldcs(&in[nb + 0 * ROW4]);
    float4 b1 = __ldcs(&in[nb + 1 * ROW4]);
    float4 b2 = __ldcs(&in[nb + 2 * ROW4]);
    float4 b3 = __ldcs(&in[nb + 3 * ROW4]);

    __stcs(&out[base + 0 * ROW4], cmp4(a0, m));
    __stcs(&out[base + 1 * ROW4], cmp4(a1, m));
    __stcs(&out[base + 2 * ROW4], cmp4(a2, m));
    __stcs(&out[base + 3 * ROW4], cmp4(a3, m));

    __stcs(&out[nb + 0 * ROW4], cmp4(b0, m));
    __stcs(&out[nb + 1 * ROW4], cmp4(b1, m));
    __stcs(&out[nb + 2 * ROW4], cmp4(b2, m));
    __stcs(&out[nb + 3 * ROW4], cmp4(b3, m));
}

extern "C" void kernel_launch(void* const* d_in, const int* in_sizes, int n_in,
                              void* d_out, int out_size) {
    // Defensive: larger tensor = inputs, smaller = medians.
    int ii = 0, mi = 1;
    if (n_in >= 2 && in_sizes[1] > in_sizes[0]) { ii = 1; mi = 0; }

    const float4* in  = (const float4*)d_in[ii];
    const float4* med = (const float4*)d_in[mi];
    float4* out = (float4*)d_out;

    // 4 col-groups x (8192 / RGRP) row-groups = 4096 blocks of 256 threads.
    unsigned grid = 4u * (NROWS / RGRP);
    binarize_kernel<<<grid, COLS4>>>(in, med, out);
}